// round 8
// baseline (speedup 1.0000x reference)
#include <cuda_runtime.h>

typedef unsigned long long u64;

// ---------- f32x2 packed helpers (sm_100+) ----------
static __device__ __forceinline__ u64 pk2(float lo, float hi) {
    u64 r; asm("mov.b64 %0, {%1, %2};" : "=l"(r) : "f"(lo), "f"(hi)); return r;
}
static __device__ __forceinline__ void upk2(u64 v, float& lo, float& hi) {
    asm("mov.b64 {%0, %1}, %2;" : "=f"(lo), "=f"(hi) : "l"(v));
}
static __device__ __forceinline__ u64 ffma2(u64 a, u64 b, u64 c) {
    u64 d; asm("fma.rn.f32x2 %0, %1, %2, %3;" : "=l"(d) : "l"(a), "l"(b), "l"(c)); return d;
}
static __device__ __forceinline__ u64 fadd2(u64 a, u64 b) {
    u64 d; asm("add.rn.f32x2 %0, %1, %2;" : "=l"(d) : "l"(a), "l"(b)); return d;
}

static __device__ __forceinline__ float softplus_fast(float v) {
    return fmaxf(v, 0.0f) + __logf(1.0f + __expf(-fabsf(v)));
}

#define C_HALF_P 0.505f
#define C_HALF_M 0.495f
#define TPB 256
#define ROWS_PER_BLOCK (TPB * 4)

// Per hidden unit j (64 of them), 8 dup-packed u64: w[j*8 + q]
//   q=0..3 : dup(W1[j][q])
//   q=4    : dup(b1[j])
//   q=5..7 : dup(0.495*V_m[j]), m=q-5
// Plus dup-packed epilogue constants.
struct ConstsPack {
    u64 w[512];
    u64 Md[12];   // dup( 0.505*(V_m W1)[k] )  (m*4+k)
    u64 Cd[3];    // dup( bias_m + 0.505*(V_m . b1) )
};

__device__ ConstsPack g_scratch;
__constant__ ConstsPack g_c;

// ---- prep kernel: build dup-packed weights into device scratch ----
__global__ void dln_prep(const float* __restrict__ W1, const float* __restrict__ b1,
                         const float* __restrict__ Wd, const float* __restrict__ bd,
                         const float* __restrict__ Wo, const float* __restrict__ bo)
{
    const int t = threadIdx.x;          // 512 threads
    {
        int j = t >> 3, q = t & 7;
        float v;
        if (q < 4) {
            v = W1[j * 4 + q];
        } else if (q == 4) {
            v = b1[j];
        } else {
            int m = q - 5;
            const float* Vm = (m < 2) ? (Wd + m * 64) : Wo;
            v = C_HALF_M * Vm[j];
        }
        g_scratch.w[t] = pk2(v, v);
    }
    if (t < 12) {
        int m = t >> 2, k = t & 3;
        const float* Vm = (m == 0) ? Wd : ((m == 1) ? (Wd + 64) : Wo);
        float s = 0.0f;
        #pragma unroll 8
        for (int j = 0; j < 64; ++j) s = fmaf(Vm[j], W1[j * 4 + k], s);
        float v = C_HALF_P * s;
        g_scratch.Md[t] = pk2(v, v);
    }
    if (t >= 12 && t < 15) {
        int m = t - 12;
        const float* Vm = (m == 0) ? Wd : ((m == 1) ? (Wd + 64) : Wo);
        float s = 0.0f;
        #pragma unroll 8
        for (int j = 0; j < 64; ++j) s = fmaf(Vm[j], b1[j], s);
        float bias = (m == 0) ? bd[0] : ((m == 1) ? bd[1] : bo[0]);
        float v = bias + C_HALF_P * s;
        g_scratch.Cd[m] = pk2(v, v);
    }
}

// ---- main kernel: row-pair packed f32x2, weights dup-packed in __constant__ ----
__global__ __launch_bounds__(TPB, 4)
void dln_kernel(const float* __restrict__ x, float* __restrict__ out, int n)
{
    const int t = threadIdx.x;
    const int rowBase = blockIdx.x * ROWS_PER_BLOCK + t;  // rows: +0,+256,+512,+768
    const float4* x4 = reinterpret_cast<const float4*>(x);
    float4* o4 = reinterpret_cast<float4*>(out);
    const u64 ABSM = 0x7fffffff7fffffffULL;

    const int r0 = rowBase;
    const int r1 = rowBase + TPB;
    const int r2 = rowBase + 2 * TPB;
    const int r3 = rowBase + 3 * TPB;

    float4 v0 = (r0 < n) ? x4[r0] : make_float4(0.f, 0.f, 0.f, 0.f);
    float4 v1 = (r1 < n) ? x4[r1] : make_float4(0.f, 0.f, 0.f, 0.f);
    float4 v2 = (r2 < n) ? x4[r2] : make_float4(0.f, 0.f, 0.f, 0.f);
    float4 v3 = (r3 < n) ? x4[r3] : make_float4(0.f, 0.f, 0.f, 0.f);

    // pack A = (row r0, row r1), pack B = (row r2, row r3)
    u64 XA[4], XB[4];
    XA[0] = pk2(v0.x, v1.x); XA[1] = pk2(v0.y, v1.y);
    XA[2] = pk2(v0.z, v1.z); XA[3] = pk2(v0.w, v1.w);
    XB[0] = pk2(v2.x, v3.x); XB[1] = pk2(v2.y, v3.y);
    XB[2] = pk2(v2.z, v3.z); XB[3] = pk2(v2.w, v3.w);

    u64 SA0 = 0ull, SA1 = 0ull, SA2 = 0ull;
    u64 SB0 = 0ull, SB1 = 0ull, SB2 = 0ull;

    #pragma unroll
    for (int j = 0; j < 64; ++j) {
        const u64 wk0 = g_c.w[j * 8 + 0];
        const u64 wk1 = g_c.w[j * 8 + 1];
        const u64 wk2 = g_c.w[j * 8 + 2];
        const u64 wk3 = g_c.w[j * 8 + 3];
        const u64 bb  = g_c.w[j * 8 + 4];
        const u64 vv0 = g_c.w[j * 8 + 5];
        const u64 vv1 = g_c.w[j * 8 + 6];
        const u64 vv2 = g_c.w[j * 8 + 7];

        u64 aA = bb;
        aA = ffma2(wk0, XA[0], aA);
        aA = ffma2(wk1, XA[1], aA);
        aA = ffma2(wk2, XA[2], aA);
        aA = ffma2(wk3, XA[3], aA);
        aA &= ABSM;                       // packed |a| for the row pair
        SA0 = ffma2(vv0, aA, SA0);
        SA1 = ffma2(vv1, aA, SA1);
        SA2 = ffma2(vv2, aA, SA2);

        u64 aB = bb;
        aB = ffma2(wk0, XB[0], aB);
        aB = ffma2(wk1, XB[1], aB);
        aB = ffma2(wk2, XB[2], aB);
        aB = ffma2(wk3, XB[3], aB);
        aB &= ABSM;
        SB0 = ffma2(vv0, aB, SB0);
        SB1 = ffma2(vv1, aB, SB1);
        SB2 = ffma2(vv2, aB, SB2);
    }

    // packed epilogue linear term: z_m = Cd_m + Md_m . x + S_m  (per row pair)
    #pragma unroll
    for (int p = 0; p < 2; ++p) {
        const u64* X  = (p == 0) ? XA : XB;
        u64 S0 = (p == 0) ? SA0 : SB0;
        u64 S1 = (p == 0) ? SA1 : SB1;
        u64 S2 = (p == 0) ? SA2 : SB2;

        u64 z0 = g_c.Cd[0], z1 = g_c.Cd[1], z2 = g_c.Cd[2];
        z0 = ffma2(g_c.Md[0], X[0], z0); z0 = ffma2(g_c.Md[1],  X[1], z0);
        z0 = ffma2(g_c.Md[2], X[2], z0); z0 = ffma2(g_c.Md[3],  X[3], z0);
        z1 = ffma2(g_c.Md[4], X[0], z1); z1 = ffma2(g_c.Md[5],  X[1], z1);
        z1 = ffma2(g_c.Md[6], X[2], z1); z1 = ffma2(g_c.Md[7],  X[3], z1);
        z2 = ffma2(g_c.Md[8], X[0], z2); z2 = ffma2(g_c.Md[9],  X[1], z2);
        z2 = ffma2(g_c.Md[10],X[2], z2); z2 = ffma2(g_c.Md[11], X[3], z2);
        z0 = fadd2(z0, S0);
        z1 = fadd2(z1, S1);
        z2 = fadd2(z2, S2);

        float z0a, z0b, z1a, z1b, z2a, z2b;
        upk2(z0, z0a, z0b);
        upk2(z1, z1a, z1b);
        upk2(z2, z2a, z2b);

        int ra = (p == 0) ? r0 : r2;
        int rb = (p == 0) ? r1 : r3;

        if (ra < n) {
            float d0 = softplus_fast(z0a);
            float d1 = softplus_fast(z1a);
            float l  = z2a;
            float4 o;
            o.x = fmaf(d0, d0, 1e-9f);
            o.y = d0 * l;
            o.z = o.y;
            o.w = fmaf(l, l, fmaf(d1, d1, 1e-9f));
            o4[ra] = o;
        }
        if (rb < n) {
            float d0 = softplus_fast(z0b);
            float d1 = softplus_fast(z1b);
            float l  = z2b;
            float4 o;
            o.x = fmaf(d0, d0, 1e-9f);
            o.y = d0 * l;
            o.z = o.y;
            o.w = fmaf(l, l, fmaf(d1, d1, 1e-9f));
            o4[rb] = o;
        }
    }
}

extern "C" void kernel_launch(void* const* d_in, const int* in_sizes, int n_in,
                              void* d_out, int out_size)
{
    const float* x  = (const float*)d_in[0];
    const float* W1 = (const float*)d_in[1];
    const float* b1 = (const float*)d_in[2];
    const float* Wd = (const float*)d_in[3];
    const float* bd = (const float*)d_in[4];
    const float* Wo = (const float*)d_in[5];
    const float* bo = (const float*)d_in[6];
    float* out = (float*)d_out;

    int n = in_sizes[0] / 4;                       // rows
    int blocks = (n + ROWS_PER_BLOCK - 1) / ROWS_PER_BLOCK;

    dln_prep<<<1, 512>>>(W1, b1, Wd, bd, Wo, bo);

    void* src = nullptr;
    cudaGetSymbolAddress(&src, g_scratch);
    cudaMemcpyToSymbolAsync(g_c, src, sizeof(ConstsPack), 0,
                            cudaMemcpyDeviceToDevice, 0);

    dln_kernel<<<blocks, TPB>>>(x, out, n);
}

// round 12
// speedup vs baseline: 1.0062x; 1.0062x over previous
#include <cuda_runtime.h>
#include <cuda_bf16.h>

typedef unsigned long long u64;
typedef unsigned int u32;

// ---------- helpers ----------
static __device__ __forceinline__ u32 bfpk(float lo, float hi) {
    u32 d; asm("cvt.rn.bf16x2.f32 %0, %1, %2;" : "=r"(d) : "f"(hi), "f"(lo)); return d;
}
static __device__ __forceinline__ float lo_bf(u32 p) { return __uint_as_float(p << 16); }
static __device__ __forceinline__ float hi_bf(u32 p) { return __uint_as_float(p & 0xFFFF0000u); }
static __device__ __forceinline__ float b2f_rn(float v) {
    return __bfloat162float(__float2bfloat16(v));
}
static __device__ __forceinline__ float softplus_fast(float v) {
    return fmaxf(v, 0.0f) + __logf(1.0f + __expf(-fabsf(v)));
}
static __device__ __forceinline__ void mma16816(float& c0, float& c1, float& c2, float& c3,
                                                u32 a0, u32 a1, u32 a2, u32 a3,
                                                u32 b0, u32 b1) {
    asm("mma.sync.aligned.m16n8k16.row.col.f32.bf16.bf16.f32 "
        "{%0,%1,%2,%3},{%4,%5,%6,%7},{%8,%9},{%0,%1,%2,%3};"
        : "+f"(c0), "+f"(c1), "+f"(c2), "+f"(c3)
        : "r"(a0), "r"(a1), "r"(a2), "r"(a3), "r"(b0), "r"(b1));
}

#define C_HALF_P 0.505f
#define C_HALF_M 0.495f

// Precomputed B-fragment tables (per fragment-id, per lane).
// t1[nb*32+lane]  : GEMM1, hidden block nb (j = 8nb + g)
// t2[idx*32+lane] : GEMM2. idx 0-3: v1 chunks (j=16idx+k), idx 4-7: v2 chunks, idx 8: linear chunk
struct Tables {
    uint2 t1[256];
    uint2 t2[288];
};
__device__ Tables g_s;

// GEMM1 B element: row k (K-slot), hidden j.
// k0-3: W1[j][k] (pack->bf16=w1); k4-7: W1[j][k-4] (w1); k8-11: w2 = W - bf16(W); k12: b_hi; k13: b_lo
static __device__ float rowB1(int k, int j, const float* W1, const float* b1) {
    if (k < 4)  return W1[j * 4 + k];
    if (k < 8)  return W1[j * 4 + (k - 4)];
    if (k < 12) { float w = W1[j * 4 + (k - 8)]; return w - b2f_rn(w); }
    if (k == 12) return b1[j];
    if (k == 13) { float b = b1[j]; return b - b2f_rn(b); }
    return 0.0f;
}

static __device__ float Mval(int m, int k, const float* W1,
                             const float* Wd, const float* Wo) {
    const float* Vm = (m < 2) ? (Wd + m * 64) : Wo;
    float s = 0.0f;
    for (int j = 0; j < 64; ++j) s = fmaf(Vm[j], W1[j * 4 + k], s);
    return C_HALF_P * s;
}
static __device__ float Cval(int m, const float* W1, const float* b1,
                             const float* Wd, const float* bd,
                             const float* Wo, const float* bo) {
    const float* Vm = (m < 2) ? (Wd + m * 64) : Wo;
    float s = 0.0f;
    for (int j = 0; j < 64; ++j) s = fmaf(Vm[j], b1[j], s);
    float bias = (m == 0) ? bd[0] : ((m == 1) ? bd[1] : bo[0]);
    return bias + C_HALF_P * s;
}

// GEMM2 B element for table idx, local K-slot k, output col m.
static __device__ float rowB2(int idx, int k, int m,
                              const float* W1, const float* b1,
                              const float* Wd, const float* bd,
                              const float* Wo, const float* bo) {
    if (m >= 3) return 0.0f;
    const float* Vm = (m < 2) ? (Wd + m * 64) : Wo;
    if (idx < 4) {                       // v1 chunks (pack rounds to bf16)
        return C_HALF_M * Vm[16 * idx + k];
    }
    if (idx < 8) {                       // v2 = v - bf16(v)
        float v = C_HALF_M * Vm[16 * (idx - 4) + k];
        return v - b2f_rn(v);
    }
    // idx == 8: linear chunk [x1*M | x2*M | x1*Mlo | c_hi c_lo 0 0]
    if (k < 8) return Mval(m, k & 3, W1, Wd, Wo);
    if (k < 12) { float M = Mval(m, k - 8, W1, Wd, Wo); return M - b2f_rn(M); }
    if (k == 12) return Cval(m, W1, b1, Wd, bd, Wo, bo);
    if (k == 13) { float C = Cval(m, W1, b1, Wd, bd, Wo, bo); return C - b2f_rn(C); }
    return 0.0f;
}

__global__ void dln_prep(const float* __restrict__ W1, const float* __restrict__ b1,
                         const float* __restrict__ Wd, const float* __restrict__ bd,
                         const float* __restrict__ Wo, const float* __restrict__ bo)
{
    const int t = threadIdx.x;           // 544 threads
    if (t < 256) {
        int nb = t >> 5, lane = t & 31, g = lane >> 2, tq = lane & 3;
        int j = 8 * nb + g;
        float r0 = rowB1(2 * tq,     j, W1, b1);
        float r1 = rowB1(2 * tq + 1, j, W1, b1);
        float r2 = rowB1(2 * tq + 8, j, W1, b1);
        float r3 = rowB1(2 * tq + 9, j, W1, b1);
        g_s.t1[t] = make_uint2(bfpk(r0, r1), bfpk(r2, r3));
    } else if (t < 544) {
        int e = t - 256;
        int idx = e >> 5, lane = e & 31, g = lane >> 2, tq = lane & 3;
        float r0 = rowB2(idx, 2 * tq,     g, W1, b1, Wd, bd, Wo, bo);
        float r1 = rowB2(idx, 2 * tq + 1, g, W1, b1, Wd, bd, Wo, bo);
        float r2 = rowB2(idx, 2 * tq + 8, g, W1, b1, Wd, bd, Wo, bo);
        float r3 = rowB2(idx, 2 * tq + 9, g, W1, b1, Wd, bd, Wo, bo);
        g_s.t2[e] = make_uint2(bfpk(r0, r1), bfpk(r2, r3));
    }
}

__global__ __launch_bounds__(256)
void dln_mma(const float* __restrict__ x, float* __restrict__ out, int n)
{
    const int lane = threadIdx.x & 31;
    const int warp = threadIdx.x >> 5;
    const int tq = lane & 3;
    const int g = lane >> 2;

    // loop-invariant B fragments
    uint2 B1f[8], B2f[9];
    #pragma unroll
    for (int i = 0; i < 8; ++i) B1f[i] = g_s.t1[i * 32 + lane];
    #pragma unroll
    for (int i = 0; i < 9; ++i) B2f[i] = g_s.t2[i * 32 + lane];

    const float4* x4 = reinterpret_cast<const float4*>(x);
    float4* o4 = reinterpret_cast<float4*>(out);
    const int ntiles = (n + 15) >> 4;
    const int nm1 = n - 1;
    const u32 ONES2 = 0x3F803F80u;     // bf16x2 (1.0, 1.0)
    const int wstride = gridDim.x * 8;

    for (int tile = blockIdx.x * 8 + warp; tile < ntiles; tile += wstride) {
        const int tokBase = tile * 16;
        const int tokA = tokBase + g;
        const int tokB = tokBase + g + 8;
        float4 xa = x4[min(tokA, nm1)];
        float4 xb = x4[min(tokB, nm1)];

        // unified A fragment (GEMM1 and linear chunk share it)
        u32 a0, a1, a2, a3;
        {
            float pa0, pa1, pb0, pb1;
            if ((tq & 1) == 0) { pa0 = xa.x; pa1 = xa.y; pb0 = xb.x; pb1 = xb.y; }
            else               { pa0 = xa.z; pa1 = xa.w; pb0 = xb.z; pb1 = xb.w; }
            u32 q1a = bfpk(pa0, pa1);
            u32 q1b = bfpk(pb0, pb1);
            if (tq < 2) {
                a0 = q1a; a1 = q1b; a2 = q1a; a3 = q1b;        // x1 slots (w1 and w2 groups)
            } else {
                a0 = bfpk(pa0 - lo_bf(q1a), pa1 - hi_bf(q1a)); // x2 slots
                a1 = bfpk(pb0 - lo_bf(q1b), pb1 - hi_bf(q1b));
                a2 = (tq == 2) ? ONES2 : 0u;                   // bias slots / zero pad
                a3 = a2;
            }
        }

        float zA0 = 0.f, zA1 = 0.f, zA2 = 0.f, zA3 = 0.f;
        float zB0 = 0.f, zB1 = 0.f, zB2 = 0.f, zB3 = 0.f;

        #pragma unroll
        for (int c = 0; c < 4; ++c) {
            // GEMM1: hidden blocks nb = 2c, 2c+1
            float c0 = 0.f, c1 = 0.f, c2 = 0.f, c3 = 0.f;
            float d0 = 0.f, d1 = 0.f, d2 = 0.f, d3 = 0.f;
            mma16816(c0, c1, c2, c3, a0, a1, a2, a3, B1f[2 * c].x, B1f[2 * c].y);
            mma16816(d0, d1, d2, d3, a0, a1, a2, a3, B1f[2 * c + 1].x, B1f[2 * c + 1].y);

            // |a| and bf16 split -> GEMM2 A fragments for K-chunk c
            float f0 = fabsf(c0), f1 = fabsf(c1), f2 = fabsf(c2), f3 = fabsf(c3);
            float e0 = fabsf(d0), e1 = fabsf(d1), e2 = fabsf(d2), e3 = fabsf(d3);
            u32 h10 = bfpk(f0, f1), h11 = bfpk(f2, f3);
            u32 h12 = bfpk(e0, e1), h13 = bfpk(e2, e3);
            u32 h20 = bfpk(f0 - lo_bf(h10), f1 - hi_bf(h10));
            u32 h21 = bfpk(f2 - lo_bf(h11), f3 - hi_bf(h11));
            u32 h22 = bfpk(e0 - lo_bf(h12), e1 - hi_bf(h12));
            u32 h23 = bfpk(e2 - lo_bf(h13), e3 - hi_bf(h13));

            mma16816(zA0, zA1, zA2, zA3, h10, h11, h12, h13, B2f[c].x,     B2f[c].y);     // v1*h1
            mma16816(zB0, zB1, zB2, zB3, h20, h21, h22, h23, B2f[c].x,     B2f[c].y);     // v1*h2
            mma16816(zB0, zB1, zB2, zB3, h10, h11, h12, h13, B2f[4 + c].x, B2f[4 + c].y); // v2*h1
        }
        // linear + bias chunk (reuses GEMM1 A fragment)
        mma16816(zA0, zA1, zA2, zA3, a0, a1, a2, a3, B2f[8].x, B2f[8].y);

        float z0 = zA0 + zB0;   // C[g][2tq]
        float z1 = zA1 + zB1;   // C[g][2tq+1]
        float z2 = zA2 + zB2;   // C[g+8][2tq]
        float z3 = zA3 + zB3;   // C[g+8][2tq+1]

        // token g's z_2 lives on lane+1 (tq=1, c0); same for token g+8
        float w0 = __shfl_down_sync(0xffffffffu, z0, 1);
        float w2 = __shfl_down_sync(0xffffffffu, z2, 1);

        if (tq == 0) {
            if (tokA < n) {
                float s0 = softplus_fast(z0);
                float s1 = softplus_fast(z1);
                float l  = w0;
                float4 o;
                o.x = fmaf(s0, s0, 1e-9f);
                o.y = s0 * l;
                o.z = o.y;
                o.w = fmaf(l, l, fmaf(s1, s1, 1e-9f));
                o4[tokA] = o;
            }
            if (tokB < n) {
                float s0 = softplus_fast(z2);
                float s1 = softplus_fast(z3);
                float l  = w2;
                float4 o;
                o.x = fmaf(s0, s0, 1e-9f);
                o.y = s0 * l;
                o.z = o.y;
                o.w = fmaf(l, l, fmaf(s1, s1, 1e-9f));
                o4[tokB] = o;
            }
        }
    }
}

extern "C" void kernel_launch(void* const* d_in, const int* in_sizes, int n_in,
                              void* d_out, int out_size)
{
    const float* x  = (const float*)d_in[0];
    const float* W1 = (const float*)d_in[1];
    const float* b1 = (const float*)d_in[2];
    const float* Wd = (const float*)d_in[3];
    const float* bd = (const float*)d_in[4];
    const float* Wo = (const float*)d_in[5];
    const float* bo = (const float*)d_in[6];
    float* out = (float*)d_out;

    int n = in_sizes[0] / 4;                 // tokens
    int ntiles = (n + 15) / 16;
    int blocks = 2048;
    int maxBlocks = (ntiles + 7) / 8;
    if (blocks > maxBlocks) blocks = maxBlocks;

    dln_prep<<<1, 544>>>(W1, b1, Wd, bd, Wo, bo);
    dln_mma<<<blocks, 256>>>(x, out, n);
}

// round 13
// speedup vs baseline: 1.0293x; 1.0229x over previous
#include <cuda_runtime.h>
#include <cuda_bf16.h>

typedef unsigned long long u64;
typedef unsigned int u32;

// ---------- packed f32x2 / bf16 helpers ----------
static __device__ __forceinline__ u64 pk2f(float lo, float hi) {
    u64 r; asm("mov.b64 %0, {%1, %2};" : "=l"(r) : "f"(lo), "f"(hi)); return r;
}
static __device__ __forceinline__ void upk2(u64 v, float& lo, float& hi) {
    asm("mov.b64 {%0, %1}, %2;" : "=f"(lo), "=f"(hi) : "l"(v));
}
static __device__ __forceinline__ u64 ffma2(u64 a, u64 b, u64 c) {
    u64 d; asm("fma.rn.f32x2 %0, %1, %2, %3;" : "=l"(d) : "l"(a), "l"(b), "l"(c)); return d;
}
static __device__ __forceinline__ u32 bfpk(float lo, float hi) {
    u32 d; asm("cvt.rn.bf16x2.f32 %0, %1, %2;" : "=r"(d) : "f"(hi), "f"(lo)); return d;
}
static __device__ __forceinline__ float lo_bf(u32 p) { return __uint_as_float(p << 16); }
static __device__ __forceinline__ float hi_bf(u32 p) { return __uint_as_float(p & 0xFFFF0000u); }
static __device__ __forceinline__ float b2f_rn(float v) {
    return __bfloat162float(__float2bfloat16(v));
}
static __device__ __forceinline__ float softplus_fast(float v) {
    return fmaxf(v, 0.0f) + __logf(1.0f + __expf(-fabsf(v)));
}
static __device__ __forceinline__ void mma16816(float& c0, float& c1, float& c2, float& c3,
                                                u32 a0, u32 a1, u32 a2, u32 a3,
                                                u32 b0, u32 b1) {
    asm("mma.sync.aligned.m16n8k16.row.col.f32.bf16.bf16.f32 "
        "{%0,%1,%2,%3},{%4,%5,%6,%7},{%8,%9},{%0,%1,%2,%3};"
        : "+f"(c0), "+f"(c1), "+f"(c2), "+f"(c3)
        : "r"(a0), "r"(a1), "r"(a2), "r"(a3), "r"(b0), "r"(b1));
}

#define C_HALF_P 0.505f
#define C_HALF_M 0.495f
#define TILES_PER_WARP 5

// ---------- FFMA-path constants (R6 layout) ----------
struct ConstsPack {
    u64 w[256];    // per j-pair jp: q0-3 (W1[2jp][q],W1[2jp+1][q]); q4 (b1 pair); q5-7 (0.495*V_m pair)
    float M[12];   // 0.505*(V_m W1)[k]
    float C[3];    // bias_m + 0.505*(V_m . b1)
    float pad;
};
__device__ ConstsPack g_scratch;
__constant__ ConstsPack g_c;

// ---------- tensor-path B-fragment tables (R12 layout) ----------
struct Tables {
    uint2 t1[256];
    uint2 t2[288];
};
__device__ Tables g_s;

__global__ void dln_prep_const(const float* __restrict__ W1, const float* __restrict__ b1,
                               const float* __restrict__ Wd, const float* __restrict__ bd,
                               const float* __restrict__ Wo, const float* __restrict__ bo)
{
    const int t = threadIdx.x;   // 256
    {
        int jp = t >> 3, q = t & 7;
        int j0 = 2 * jp, j1 = j0 + 1;
        float lo, hi;
        if (q < 4)      { lo = W1[j0 * 4 + q]; hi = W1[j1 * 4 + q]; }
        else if (q == 4){ lo = b1[j0]; hi = b1[j1]; }
        else {
            int m = q - 5;
            const float* Vm = (m < 2) ? (Wd + m * 64) : Wo;
            lo = C_HALF_M * Vm[j0]; hi = C_HALF_M * Vm[j1];
        }
        g_scratch.w[t] = pk2f(lo, hi);
    }
    if (t < 12) {
        int m = t >> 2, k = t & 3;
        const float* Vm = (m == 0) ? Wd : ((m == 1) ? (Wd + 64) : Wo);
        float s = 0.0f;
        for (int j = 0; j < 64; ++j) s = fmaf(Vm[j], W1[j * 4 + k], s);
        g_scratch.M[t] = C_HALF_P * s;
    }
    if (t >= 12 && t < 15) {
        int m = t - 12;
        const float* Vm = (m == 0) ? Wd : ((m == 1) ? (Wd + 64) : Wo);
        float s = 0.0f;
        for (int j = 0; j < 64; ++j) s = fmaf(Vm[j], b1[j], s);
        float bias = (m == 0) ? bd[0] : ((m == 1) ? bd[1] : bo[0]);
        g_scratch.C[m] = bias + C_HALF_P * s;
    }
}

static __device__ float rowB1(int k, int j, const float* W1, const float* b1) {
    if (k < 4)  return W1[j * 4 + k];
    if (k < 8)  return W1[j * 4 + (k - 4)];
    if (k < 12) { float w = W1[j * 4 + (k - 8)]; return w - b2f_rn(w); }
    if (k == 12) return b1[j];
    if (k == 13) { float b = b1[j]; return b - b2f_rn(b); }
    return 0.0f;
}
static __device__ float Mval(int m, int k, const float* W1, const float* Wd, const float* Wo) {
    const float* Vm = (m < 2) ? (Wd + m * 64) : Wo;
    float s = 0.0f;
    for (int j = 0; j < 64; ++j) s = fmaf(Vm[j], W1[j * 4 + k], s);
    return C_HALF_P * s;
}
static __device__ float Cval(int m, const float* W1, const float* b1,
                             const float* Wd, const float* bd,
                             const float* Wo, const float* bo) {
    const float* Vm = (m < 2) ? (Wd + m * 64) : Wo;
    float s = 0.0f;
    for (int j = 0; j < 64; ++j) s = fmaf(Vm[j], b1[j], s);
    float bias = (m == 0) ? bd[0] : ((m == 1) ? bd[1] : bo[0]);
    return bias + C_HALF_P * s;
}
static __device__ float rowB2(int idx, int k, int m,
                              const float* W1, const float* b1,
                              const float* Wd, const float* bd,
                              const float* Wo, const float* bo) {
    if (m >= 3) return 0.0f;
    const float* Vm = (m < 2) ? (Wd + m * 64) : Wo;
    if (idx < 4) return C_HALF_M * Vm[16 * idx + k];
    if (idx < 8) { float v = C_HALF_M * Vm[16 * (idx - 4) + k]; return v - b2f_rn(v); }
    if (k < 8) return Mval(m, k & 3, W1, Wd, Wo);
    if (k < 12) { float M = Mval(m, k - 8, W1, Wd, Wo); return M - b2f_rn(M); }
    if (k == 12) return Cval(m, W1, b1, Wd, bd, Wo, bo);
    if (k == 13) { float C = Cval(m, W1, b1, Wd, bd, Wo, bo); return C - b2f_rn(C); }
    return 0.0f;
}

__global__ void dln_prep_frags(const float* __restrict__ W1, const float* __restrict__ b1,
                               const float* __restrict__ Wd, const float* __restrict__ bd,
                               const float* __restrict__ Wo, const float* __restrict__ bo)
{
    const int t = threadIdx.x;   // 544
    if (t < 256) {
        int nb = t >> 5, lane = t & 31, g = lane >> 2, tq = lane & 3;
        int j = 8 * nb + g;
        g_s.t1[t] = make_uint2(bfpk(rowB1(2 * tq, j, W1, b1), rowB1(2 * tq + 1, j, W1, b1)),
                               bfpk(rowB1(2 * tq + 8, j, W1, b1), rowB1(2 * tq + 9, j, W1, b1)));
    } else if (t < 544) {
        int e = t - 256;
        int idx = e >> 5, lane = e & 31, g = lane >> 2, tq = lane & 3;
        g_s.t2[e] = make_uint2(
            bfpk(rowB2(idx, 2 * tq, g, W1, b1, Wd, bd, Wo, bo),
                 rowB2(idx, 2 * tq + 1, g, W1, b1, Wd, bd, Wo, bo)),
            bfpk(rowB2(idx, 2 * tq + 8, g, W1, b1, Wd, bd, Wo, bo),
                 rowB2(idx, 2 * tq + 9, g, W1, b1, Wd, bd, Wo, bo)));
    }
}

static __device__ __forceinline__ void epi_store(float4* o4, int tok, int lim,
                                                 float z0, float z1, float l) {
    if (tok < lim) {
        float d0 = softplus_fast(z0);
        float d1 = softplus_fast(z1);
        float4 o;
        o.x = fmaf(d0, d0, 1e-9f);
        o.y = d0 * l;
        o.z = o.y;
        o.w = fmaf(l, l, fmaf(d1, d1, 1e-9f));
        o4[tok] = o;
    }
}

// ---------- fused kernel: warps 0-3 tensor path, warps 4-7 FFMA path ----------
__global__ __launch_bounds__(256, 3)
void dln_fused(const float* __restrict__ x, float* __restrict__ out,
               int n, int nT, int nTiles)
{
    const int lane = threadIdx.x & 31;
    const int warp = threadIdx.x >> 5;
    const float4* x4 = reinterpret_cast<const float4*>(x);
    float4* o4 = reinterpret_cast<float4*>(out);
    const int nm1 = n - 1;

    if (warp < 4) {
        // ================= tensor path: tokens [0, nT) =================
        const int tq = lane & 3;
        const int g = lane >> 2;
        uint2 B1f[8], B2f[9];
        #pragma unroll
        for (int i = 0; i < 8; ++i) B1f[i] = g_s.t1[i * 32 + lane];
        #pragma unroll
        for (int i = 0; i < 9; ++i) B2f[i] = g_s.t2[i * 32 + lane];

        const u32 ONES2 = 0x3F803F80u;
        const int gw = blockIdx.x * 4 + warp;

        #pragma unroll 1
        for (int ti = 0; ti < TILES_PER_WARP; ++ti) {
            const int tile = gw * TILES_PER_WARP + ti;
            if (tile >= nTiles) break;
            const int tokBase = tile * 16;
            const int tokA = tokBase + g;
            const int tokB = tokBase + g + 8;
            float4 xa = x4[min(tokA, nm1)];
            float4 xb = x4[min(tokB, nm1)];

            u32 a0, a1, a2, a3;
            {
                float pa0, pa1, pb0, pb1;
                if ((tq & 1) == 0) { pa0 = xa.x; pa1 = xa.y; pb0 = xb.x; pb1 = xb.y; }
                else               { pa0 = xa.z; pa1 = xa.w; pb0 = xb.z; pb1 = xb.w; }
                u32 q1a = bfpk(pa0, pa1);
                u32 q1b = bfpk(pb0, pb1);
                if (tq < 2) {
                    a0 = q1a; a1 = q1b; a2 = q1a; a3 = q1b;
                } else {
                    a0 = bfpk(pa0 - lo_bf(q1a), pa1 - hi_bf(q1a));
                    a1 = bfpk(pb0 - lo_bf(q1b), pb1 - hi_bf(q1b));
                    a2 = (tq == 2) ? ONES2 : 0u;
                    a3 = a2;
                }
            }

            float zA0 = 0.f, zA1 = 0.f, zA2 = 0.f, zA3 = 0.f;
            float zB0 = 0.f, zB1 = 0.f, zB2 = 0.f, zB3 = 0.f;

            #pragma unroll
            for (int c = 0; c < 4; ++c) {
                float c0 = 0.f, c1 = 0.f, c2 = 0.f, c3 = 0.f;
                float d0 = 0.f, d1 = 0.f, d2 = 0.f, d3 = 0.f;
                mma16816(c0, c1, c2, c3, a0, a1, a2, a3, B1f[2 * c].x, B1f[2 * c].y);
                mma16816(d0, d1, d2, d3, a0, a1, a2, a3, B1f[2 * c + 1].x, B1f[2 * c + 1].y);

                float f0 = fabsf(c0), f1 = fabsf(c1), f2 = fabsf(c2), f3 = fabsf(c3);
                float e0 = fabsf(d0), e1 = fabsf(d1), e2 = fabsf(d2), e3 = fabsf(d3);
                u32 h10 = bfpk(f0, f1), h11 = bfpk(f2, f3);
                u32 h12 = bfpk(e0, e1), h13 = bfpk(e2, e3);
                u32 h20 = bfpk(f0 - lo_bf(h10), f1 - hi_bf(h10));
                u32 h21 = bfpk(f2 - lo_bf(h11), f3 - hi_bf(h11));
                u32 h22 = bfpk(e0 - lo_bf(h12), e1 - hi_bf(h12));
                u32 h23 = bfpk(e2 - lo_bf(h13), e3 - hi_bf(h13));

                mma16816(zA0, zA1, zA2, zA3, h10, h11, h12, h13, B2f[c].x, B2f[c].y);
                mma16816(zB0, zB1, zB2, zB3, h20, h21, h22, h23, B2f[c].x, B2f[c].y);
                mma16816(zB0, zB1, zB2, zB3, h10, h11, h12, h13, B2f[4 + c].x, B2f[4 + c].y);
            }
            mma16816(zA0, zA1, zA2, zA3, a0, a1, a2, a3, B2f[8].x, B2f[8].y);

            float z0 = zA0 + zB0;
            float z1 = zA1 + zB1;
            float z2 = zA2 + zB2;
            float z3 = zA3 + zB3;

            float w0 = __shfl_down_sync(0xffffffffu, z0, 1);
            float w2 = __shfl_down_sync(0xffffffffu, z2, 1);

            if (tq == 0) {
                epi_store(o4, tokA, nT, z0, z1, w0);
                epi_store(o4, tokB, nT, z2, z3, w2);
            }
        }
    } else {
        // ================= FFMA path: tokens [nT, n) =================
        const int gf = blockIdx.x * 4 + (warp - 4);
        const int rowStart = nT + gf * 64;
        const int r0 = rowStart + lane;
        const int r1 = rowStart + 32 + lane;
        if (r0 >= n) return;

        float4 va = x4[min(r0, nm1)];
        float4 vb = x4[min(r1, nm1)];
        u64 X0[4], X1[4];
        X0[0] = pk2f(va.x, va.x); X0[1] = pk2f(va.y, va.y);
        X0[2] = pk2f(va.z, va.z); X0[3] = pk2f(va.w, va.w);
        X1[0] = pk2f(vb.x, vb.x); X1[1] = pk2f(vb.y, vb.y);
        X1[2] = pk2f(vb.z, vb.z); X1[3] = pk2f(vb.w, vb.w);

        const u64 ABSM = 0x7fffffff7fffffffULL;
        u64 S00 = 0ull, S01 = 0ull, S02 = 0ull;
        u64 S10 = 0ull, S11 = 0ull, S12 = 0ull;

        #pragma unroll
        for (int jp = 0; jp < 32; ++jp) {
            const u64 wk0 = g_c.w[jp * 8 + 0];
            const u64 wk1 = g_c.w[jp * 8 + 1];
            const u64 wk2 = g_c.w[jp * 8 + 2];
            const u64 wk3 = g_c.w[jp * 8 + 3];
            const u64 bb  = g_c.w[jp * 8 + 4];
            const u64 v0  = g_c.w[jp * 8 + 5];
            const u64 v1  = g_c.w[jp * 8 + 6];
            const u64 v2  = g_c.w[jp * 8 + 7];

            u64 a0 = bb;
            a0 = ffma2(wk0, X0[0], a0);
            a0 = ffma2(wk1, X0[1], a0);
            a0 = ffma2(wk2, X0[2], a0);
            a0 = ffma2(wk3, X0[3], a0);
            a0 &= ABSM;
            S00 = ffma2(v0, a0, S00);
            S01 = ffma2(v1, a0, S01);
            S02 = ffma2(v2, a0, S02);

            u64 a1 = bb;
            a1 = ffma2(wk0, X1[0], a1);
            a1 = ffma2(wk1, X1[1], a1);
            a1 = ffma2(wk2, X1[2], a1);
            a1 = ffma2(wk3, X1[3], a1);
            a1 &= ABSM;
            S10 = ffma2(v0, a1, S10);
            S11 = ffma2(v1, a1, S11);
            S12 = ffma2(v2, a1, S12);
        }

        const float m0 = g_c.M[0], m1 = g_c.M[1], m2  = g_c.M[2],  m3  = g_c.M[3];
        const float m4 = g_c.M[4], m5 = g_c.M[5], m6  = g_c.M[6],  m7  = g_c.M[7];
        const float m8 = g_c.M[8], m9 = g_c.M[9], m10 = g_c.M[10], m11 = g_c.M[11];
        const float c0 = g_c.C[0], c1 = g_c.C[1], c2  = g_c.C[2];

        #pragma unroll
        for (int i = 0; i < 2; ++i) {
            int r = (i == 0) ? r0 : r1;
            if (r >= n) continue;
            u64 T0 = (i == 0) ? S00 : S10;
            u64 T1 = (i == 0) ? S01 : S11;
            u64 T2 = (i == 0) ? S02 : S12;
            const u64* Xi = (i == 0) ? X0 : X1;

            float lo_, hi_;
            upk2(T0, lo_, hi_); float s0 = lo_ + hi_;
            upk2(T1, lo_, hi_); float s1 = lo_ + hi_;
            upk2(T2, lo_, hi_); float s2 = lo_ + hi_;

            float xk0, xk1, xk2, xk3, junk;
            upk2(Xi[0], xk0, junk);
            upk2(Xi[1], xk1, junk);
            upk2(Xi[2], xk2, junk);
            upk2(Xi[3], xk3, junk);

            float z0 = fmaf(m3,  xk3, fmaf(m2,  xk2, fmaf(m1, xk1, fmaf(m0, xk0, c0)))) + s0;
            float z1 = fmaf(m7,  xk3, fmaf(m6,  xk2, fmaf(m5, xk1, fmaf(m4, xk0, c1)))) + s1;
            float z2 = fmaf(m11, xk3, fmaf(m10, xk2, fmaf(m9, xk1, fmaf(m8, xk0, c2)))) + s2;

            epi_store(o4, r, n, z0, z1, z2);
        }
    }
}

extern "C" void kernel_launch(void* const* d_in, const int* in_sizes, int n_in,
                              void* d_out, int out_size)
{
    const float* x  = (const float*)d_in[0];
    const float* W1 = (const float*)d_in[1];
    const float* b1 = (const float*)d_in[2];
    const float* Wd = (const float*)d_in[3];
    const float* bd = (const float*)d_in[4];
    const float* Wo = (const float*)d_in[5];
    const float* bo = (const float*)d_in[6];
    float* out = (float*)d_out;

    int n = in_sizes[0] / 4;                       // tokens
    // per block: tensor 4 warps * 5 tiles * 16 = 320 tokens, ffma 4 warps * 64 = 256 tokens
    int B = (n + 575) / 576;
    long long nF = (long long)B * 256;
    int nT = (int)((nF >= n) ? 0 : (n - nF));      // ffma takes the tail
    int nTiles = (nT + 15) / 16;

    dln_prep_const<<<1, 256>>>(W1, b1, Wd, bd, Wo, bo);
    dln_prep_frags<<<1, 544>>>(W1, b1, Wd, bd, Wo, bo);

    void* src = nullptr;
    cudaGetSymbolAddress(&src, g_scratch);
    cudaMemcpyToSymbolAsync(g_c, src, sizeof(ConstsPack), 0,
                            cudaMemcpyDeviceToDevice, 0);

    dln_fused<<<B, 256>>>(x, out, n, nT, nTiles);
}

// round 15
// speedup vs baseline: 1.0387x; 1.0091x over previous
#include <cuda_runtime.h>
#include <cuda_bf16.h>

typedef unsigned long long u64;
typedef unsigned int u32;

// ---------- helpers ----------
static __device__ __forceinline__ u32 bfpk(float lo, float hi) {
    u32 d; asm("cvt.rn.bf16x2.f32 %0, %1, %2;" : "=r"(d) : "f"(hi), "f"(lo)); return d;
}
static __device__ __forceinline__ float lo_bf(u32 p) { return __uint_as_float(p << 16); }
static __device__ __forceinline__ float hi_bf(u32 p) { return __uint_as_float(p & 0xFFFF0000u); }
static __device__ __forceinline__ float b2f_rn(float v) {
    return __bfloat162float(__float2bfloat16(v));
}
static __device__ __forceinline__ float softplus_fast(float v) {
    return fmaxf(v, 0.0f) + __logf(1.0f + __expf(-fabsf(v)));
}
static __device__ __forceinline__ void mma16816(float& c0, float& c1, float& c2, float& c3,
                                                u32 a0, u32 a1, u32 a2, u32 a3,
                                                u32 b0, u32 b1) {
    asm("mma.sync.aligned.m16n8k16.row.col.f32.bf16.bf16.f32 "
        "{%0,%1,%2,%3},{%4,%5,%6,%7},{%8,%9},{%0,%1,%2,%3};"
        : "+f"(c0), "+f"(c1), "+f"(c2), "+f"(c3)
        : "r"(a0), "r"(a1), "r"(a2), "r"(a3), "r"(b0), "r"(b1));
}

#define C_HALF_P 0.505f
#define C_HALF_M 0.495f
#define ABS2 0x7FFF7FFFu

// ---------- B-fragment tables ----------
struct Tables {
    uint2 t1[256];
    uint2 t2[288];
};
__device__ Tables g_s;

static __device__ float rowB1(int k, int j, const float* W1, const float* b1) {
    if (k < 4)  return W1[j * 4 + k];
    if (k < 8)  return W1[j * 4 + (k - 4)];
    if (k < 12) { float w = W1[j * 4 + (k - 8)]; return w - b2f_rn(w); }
    if (k == 12) return b1[j];
    if (k == 13) { float b = b1[j]; return b - b2f_rn(b); }
    return 0.0f;
}
static __device__ float Mval(int m, int k, const float* W1, const float* Wd, const float* Wo) {
    const float* Vm = (m < 2) ? (Wd + m * 64) : Wo;
    float s = 0.0f;
    for (int j = 0; j < 64; ++j) s = fmaf(Vm[j], W1[j * 4 + k], s);
    return C_HALF_P * s;
}
static __device__ float Cval(int m, const float* W1, const float* b1,
                             const float* Wd, const float* bd,
                             const float* Wo, const float* bo) {
    const float* Vm = (m < 2) ? (Wd + m * 64) : Wo;
    float s = 0.0f;
    for (int j = 0; j < 64; ++j) s = fmaf(Vm[j], b1[j], s);
    float bias = (m == 0) ? bd[0] : ((m == 1) ? bd[1] : bo[0]);
    return bias + C_HALF_P * s;
}
static __device__ float rowB2(int idx, int k, int m,
                              const float* W1, const float* b1,
                              const float* Wd, const float* bd,
                              const float* Wo, const float* bo) {
    if (m >= 3) return 0.0f;
    const float* Vm = (m < 2) ? (Wd + m * 64) : Wo;
    if (idx < 4) return C_HALF_M * Vm[16 * idx + k];
    if (idx < 8) { float v = C_HALF_M * Vm[16 * (idx - 4) + k]; return v - b2f_rn(v); }
    if (k < 8) return Mval(m, k & 3, W1, Wd, Wo);
    if (k < 12) { float M = Mval(m, k - 8, W1, Wd, Wo); return M - b2f_rn(M); }
    if (k == 12) return Cval(m, W1, b1, Wd, bd, Wo, bo);
    if (k == 13) { float C = Cval(m, W1, b1, Wd, bd, Wo, bo); return C - b2f_rn(C); }
    return 0.0f;
}

__global__ void dln_prep(const float* __restrict__ W1, const float* __restrict__ b1,
                         const float* __restrict__ Wd, const float* __restrict__ bd,
                         const float* __restrict__ Wo, const float* __restrict__ bo)
{
    const int t = threadIdx.x;   // 544
    if (t < 256) {
        int nb = t >> 5, lane = t & 31, g = lane >> 2, tq = lane & 3;
        int j = 8 * nb + g;
        g_s.t1[t] = make_uint2(bfpk(rowB1(2 * tq, j, W1, b1), rowB1(2 * tq + 1, j, W1, b1)),
                               bfpk(rowB1(2 * tq + 8, j, W1, b1), rowB1(2 * tq + 9, j, W1, b1)));
    } else if (t < 544) {
        int e = t - 256;
        int idx = e >> 5, lane = e & 31, g = lane >> 2, tq = lane & 3;
        g_s.t2[e] = make_uint2(
            bfpk(rowB2(idx, 2 * tq, g, W1, b1, Wd, bd, Wo, bo),
                 rowB2(idx, 2 * tq + 1, g, W1, b1, Wd, bd, Wo, bo)),
            bfpk(rowB2(idx, 2 * tq + 8, g, W1, b1, Wd, bd, Wo, bo),
                 rowB2(idx, 2 * tq + 9, g, W1, b1, Wd, bd, Wo, bo)));
    }
}

__global__ __launch_bounds__(128, 6)
void dln_mma(const float* __restrict__ x, float* __restrict__ out, int n)
{
    const int lane = threadIdx.x & 31;
    const int warp = threadIdx.x >> 5;
    const int tq = lane & 3;
    const int g = lane >> 2;

    uint2 B1f[8], B2f[9];
    #pragma unroll
    for (int i = 0; i < 8; ++i) B1f[i] = g_s.t1[i * 32 + lane];
    #pragma unroll
    for (int i = 0; i < 9; ++i) B2f[i] = g_s.t2[i * 32 + lane];

    const float4* x4 = reinterpret_cast<const float4*>(x);
    float4* o4 = reinterpret_cast<float4*>(out);
    const int ntiles = (n + 15) >> 4;
    const int nm1 = n - 1;
    const u32 ONES2 = 0x3F803F80u;
    const int wstride = gridDim.x * 4;

    int tile = blockIdx.x * 4 + warp;
    // prefetch first tile's x
    float4 xa = x4[min(tile * 16 + g, nm1)];
    float4 xb = x4[min(tile * 16 + g + 8, nm1)];

    for (; tile < ntiles; tile += wstride) {
        const int tokA = tile * 16 + g;
        const int tokB = tile * 16 + g + 8;

        // unified A fragment (GEMM1 + linear chunk)
        u32 a0, a1, a2, a3;
        {
            float pa0, pa1, pb0, pb1;
            if ((tq & 1) == 0) { pa0 = xa.x; pa1 = xa.y; pb0 = xb.x; pb1 = xb.y; }
            else               { pa0 = xa.z; pa1 = xa.w; pb0 = xb.z; pb1 = xb.w; }
            u32 q1a = bfpk(pa0, pa1);
            u32 q1b = bfpk(pb0, pb1);
            if (tq < 2) {
                a0 = q1a; a1 = q1b; a2 = q1a; a3 = q1b;
            } else {
                a0 = bfpk(pa0 - lo_bf(q1a), pa1 - hi_bf(q1a));
                a1 = bfpk(pb0 - lo_bf(q1b), pb1 - hi_bf(q1b));
                a2 = (tq == 2) ? ONES2 : 0u;
                a3 = a2;
            }
        }

        // prefetch next tile's x NOW (hides DRAM under mma chains)
        {
            int nt = tile + wstride;
            int pbase = (nt < ntiles) ? nt * 16 : 0;
            xa = x4[min(pbase + g, nm1)];
            xb = x4[min(pbase + g + 8, nm1)];
        }

        float zA0 = 0.f, zA1 = 0.f, zA2 = 0.f, zA3 = 0.f;
        float zB0 = 0.f, zB1 = 0.f, zB2 = 0.f, zB3 = 0.f;

        #pragma unroll
        for (int c = 0; c < 4; ++c) {
            float c0 = 0.f, c1 = 0.f, c2 = 0.f, c3 = 0.f;
            float d0 = 0.f, d1 = 0.f, d2 = 0.f, d3 = 0.f;
            mma16816(c0, c1, c2, c3, a0, a1, a2, a3, B1f[2 * c].x, B1f[2 * c].y);
            mma16816(d0, d1, d2, d3, a0, a1, a2, a3, B1f[2 * c + 1].x, B1f[2 * c + 1].y);

            // packed |.|: cvt then one LOP3 clears both sign bits
            u32 h10 = bfpk(c0, c1) & ABS2;
            u32 h11 = bfpk(c2, c3) & ABS2;
            u32 h12 = bfpk(d0, d1) & ABS2;
            u32 h13 = bfpk(d2, d3) & ABS2;
            // h2 = |v| - bf16(|v|)  (abs folds into FADD operand modifier)
            u32 h20 = bfpk(fabsf(c0) - lo_bf(h10), fabsf(c1) - hi_bf(h10));
            u32 h21 = bfpk(fabsf(c2) - lo_bf(h11), fabsf(c3) - hi_bf(h11));
            u32 h22 = bfpk(fabsf(d0) - lo_bf(h12), fabsf(d1) - hi_bf(h12));
            u32 h23 = bfpk(fabsf(d2) - lo_bf(h13), fabsf(d3) - hi_bf(h13));

            mma16816(zA0, zA1, zA2, zA3, h10, h11, h12, h13, B2f[c].x, B2f[c].y);     // v1*h1
            mma16816(zB0, zB1, zB2, zB3, h20, h21, h22, h23, B2f[c].x, B2f[c].y);     // v1*h2
            mma16816(zB0, zB1, zB2, zB3, h10, h11, h12, h13, B2f[4 + c].x, B2f[4 + c].y); // v2*h1
        }
        mma16816(zA0, zA1, zA2, zA3, a0, a1, a2, a3, B2f[8].x, B2f[8].y);  // linear+bias

        float z0 = zA0 + zB0;
        float z1 = zA1 + zB1;
        float z2 = zA2 + zB2;
        float z3 = zA3 + zB3;

        float w0 = __shfl_down_sync(0xffffffffu, z0, 1);
        float w2 = __shfl_down_sync(0xffffffffu, z2, 1);

        if (tq == 0) {
            if (tokA < n) {
                float s0 = softplus_fast(z0);
                float s1 = softplus_fast(z1);
                float4 o;
                o.x = fmaf(s0, s0, 1e-9f);
                o.y = s0 * w0;
                o.z = o.y;
                o.w = fmaf(w0, w0, fmaf(s1, s1, 1e-9f));
                o4[tokA] = o;
            }
            if (tokB < n) {
                float s0 = softplus_fast(z2);
                float s1 = softplus_fast(z3);
                float4 o;
                o.x = fmaf(s0, s0, 1e-9f);
                o.y = s0 * w2;
                o.z = o.y;
                o.w = fmaf(w2, w2, fmaf(s1, s1, 1e-9f));
                o4[tokB] = o;
            }
        }
    }
}

extern "C" void kernel_launch(void* const* d_in, const int* in_sizes, int n_in,
                              void* d_out, int out_size)
{
    const float* x  = (const float*)d_in[0];
    const float* W1 = (const float*)d_in[1];
    const float* b1 = (const float*)d_in[2];
    const float* Wd = (const float*)d_in[3];
    const float* bd = (const float*)d_in[4];
    const float* Wo = (const float*)d_in[5];
    const float* bo = (const float*)d_in[6];
    float* out = (float*)d_out;

    int n = in_sizes[0] / 4;                 // tokens
    int ntiles = (n + 15) / 16;
    // one wave: 148 SMs x 6 blocks (reg-limited) -> each warp grid-strides
    int blocks = 148 * 6;
    int maxBlocks = (ntiles + 3) / 4;
    if (blocks > maxBlocks) blocks = maxBlocks;

    dln_prep<<<1, 544>>>(W1, b1, Wd, bd, Wo, bo);
    dln_mma<<<blocks, 128>>>(x, out, n);
}

// round 16
// speedup vs baseline: 1.0603x; 1.0208x over previous
#include <cuda_runtime.h>
#include <cuda_bf16.h>

typedef unsigned long long u64;
typedef unsigned int u32;

// ---------- helpers ----------
static __device__ __forceinline__ u32 bfpk(float lo, float hi) {
    u32 d; asm("cvt.rn.bf16x2.f32 %0, %1, %2;" : "=r"(d) : "f"(hi), "f"(lo)); return d;
}
static __device__ __forceinline__ float lo_bf(u32 p) { return __uint_as_float(p << 16); }
static __device__ __forceinline__ float hi_bf(u32 p) { return __uint_as_float(p & 0xFFFF0000u); }
static __device__ __forceinline__ float b2f_rn(float v) {
    return __bfloat162float(__float2bfloat16(v));
}
static __device__ __forceinline__ float softplus_fast(float v) {
    return fmaxf(v, 0.0f) + __logf(1.0f + __expf(-fabsf(v)));
}
static __device__ __forceinline__ void mma16816(float& c0, float& c1, float& c2, float& c3,
                                                u32 a0, u32 a1, u32 a2, u32 a3,
                                                u32 b0, u32 b1) {
    asm("mma.sync.aligned.m16n8k16.row.col.f32.bf16.bf16.f32 "
        "{%0,%1,%2,%3},{%4,%5,%6,%7},{%8,%9},{%0,%1,%2,%3};"
        : "+f"(c0), "+f"(c1), "+f"(c2), "+f"(c3)
        : "r"(a0), "r"(a1), "r"(a2), "r"(a3), "r"(b0), "r"(b1));
}

#define C_HALF_P 0.505f
#define C_HALF_M 0.495f
#define ABS2 0x7FFF7FFFu

// ---------- B-fragment tables ----------
struct Tables {
    uint2 t1[256];
    uint2 t2[288];
};
__device__ Tables g_s;

static __device__ float rowB1(int k, int j, const float* W1, const float* b1) {
    if (k < 4)  return W1[j * 4 + k];
    if (k < 8)  return W1[j * 4 + (k - 4)];
    if (k < 12) { float w = W1[j * 4 + (k - 8)]; return w - b2f_rn(w); }
    if (k == 12) return b1[j];
    if (k == 13) { float b = b1[j]; return b - b2f_rn(b); }
    return 0.0f;
}
static __device__ float Mval(int m, int k, const float* W1, const float* Wd, const float* Wo) {
    const float* Vm = (m < 2) ? (Wd + m * 64) : Wo;
    float s = 0.0f;
    for (int j = 0; j < 64; ++j) s = fmaf(Vm[j], W1[j * 4 + k], s);
    return C_HALF_P * s;
}
static __device__ float Cval(int m, const float* W1, const float* b1,
                             const float* Wd, const float* bd,
                             const float* Wo, const float* bo) {
    const float* Vm = (m < 2) ? (Wd + m * 64) : Wo;
    float s = 0.0f;
    for (int j = 0; j < 64; ++j) s = fmaf(Vm[j], b1[j], s);
    float bias = (m == 0) ? bd[0] : ((m == 1) ? bd[1] : bo[0]);
    return bias + C_HALF_P * s;
}
static __device__ float rowB2(int idx, int k, int m,
                              const float* W1, const float* b1,
                              const float* Wd, const float* bd,
                              const float* Wo, const float* bo) {
    if (m >= 3) return 0.0f;
    const float* Vm = (m < 2) ? (Wd + m * 64) : Wo;
    if (idx < 4) return C_HALF_M * Vm[16 * idx + k];
    if (idx < 8) { float v = C_HALF_M * Vm[16 * (idx - 4) + k]; return v - b2f_rn(v); }
    if (k < 8) return Mval(m, k & 3, W1, Wd, Wo);
    if (k < 12) { float M = Mval(m, k - 8, W1, Wd, Wo); return M - b2f_rn(M); }
    if (k == 12) return Cval(m, W1, b1, Wd, bd, Wo, bo);
    if (k == 13) { float C = Cval(m, W1, b1, Wd, bd, Wo, bo); return C - b2f_rn(C); }
    return 0.0f;
}

__global__ void dln_prep(const float* __restrict__ W1, const float* __restrict__ b1,
                         const float* __restrict__ Wd, const float* __restrict__ bd,
                         const float* __restrict__ Wo, const float* __restrict__ bo)
{
    const int t = threadIdx.x;   // 544
    if (t < 256) {
        int nb = t >> 5, lane = t & 31, g = lane >> 2, tq = lane & 3;
        int j = 8 * nb + g;
        g_s.t1[t] = make_uint2(bfpk(rowB1(2 * tq, j, W1, b1), rowB1(2 * tq + 1, j, W1, b1)),
                               bfpk(rowB1(2 * tq + 8, j, W1, b1), rowB1(2 * tq + 9, j, W1, b1)));
    } else if (t < 544) {
        int e = t - 256;
        int idx = e >> 5, lane = e & 31, g = lane >> 2, tq = lane & 3;
        g_s.t2[e] = make_uint2(
            bfpk(rowB2(idx, 2 * tq, g, W1, b1, Wd, bd, Wo, bo),
                 rowB2(idx, 2 * tq + 1, g, W1, b1, Wd, bd, Wo, bo)),
            bfpk(rowB2(idx, 2 * tq + 8, g, W1, b1, Wd, bd, Wo, bo),
                 rowB2(idx, 2 * tq + 9, g, W1, b1, Wd, bd, Wo, bo)));
    }
}

__global__ __launch_bounds__(128, 6)
void dln_mma(const float* __restrict__ x, float* __restrict__ out, int n)
{
    const int lane = threadIdx.x & 31;
    const int warp = threadIdx.x >> 5;
    const int tq = lane & 3;
    const int g = lane >> 2;

    uint2 B1f[8], B2f[9];
    #pragma unroll
    for (int i = 0; i < 8; ++i) B1f[i] = g_s.t1[i * 32 + lane];
    #pragma unroll
    for (int i = 0; i < 9; ++i) B2f[i] = g_s.t2[i * 32 + lane];

    const float4* x4 = reinterpret_cast<const float4*>(x);
    float4* o4 = reinterpret_cast<float4*>(out);
    const int ntiles = (n + 15) >> 4;
    const int nm1 = n - 1;
    const u32 ONES2 = 0x3F803F80u;
    const int wstride = gridDim.x * 4;

    int tile = blockIdx.x * 4 + warp;
    // prefetch first tile's x
    float4 xa = x4[min(tile * 16 + g, nm1)];
    float4 xb = x4[min(tile * 16 + g + 8, nm1)];

    for (; tile < ntiles; tile += wstride) {
        const int tokA = tile * 16 + g;
        const int tokB = tile * 16 + g + 8;

        // unified A fragment (GEMM1 + linear chunk)
        u32 a0, a1, a2, a3;
        {
            float pa0, pa1, pb0, pb1;
            if ((tq & 1) == 0) { pa0 = xa.x; pa1 = xa.y; pb0 = xb.x; pb1 = xb.y; }
            else               { pa0 = xa.z; pa1 = xa.w; pb0 = xb.z; pb1 = xb.w; }
            u32 q1a = bfpk(pa0, pa1);
            u32 q1b = bfpk(pb0, pb1);
            if (tq < 2) {
                a0 = q1a; a1 = q1b; a2 = q1a; a3 = q1b;
            } else {
                a0 = bfpk(pa0 - lo_bf(q1a), pa1 - hi_bf(q1a));
                a1 = bfpk(pb0 - lo_bf(q1b), pb1 - hi_bf(q1b));
                a2 = (tq == 2) ? ONES2 : 0u;
                a3 = a2;
            }
        }

        // prefetch next tile's x NOW (hides DRAM under mma chains)
        {
            int nt = tile + wstride;
            int pbase = (nt < ntiles) ? nt * 16 : 0;
            xa = x4[min(pbase + g, nm1)];
            xb = x4[min(pbase + g + 8, nm1)];
        }

        float zA0 = 0.f, zA1 = 0.f, zA2 = 0.f, zA3 = 0.f;
        float zB0 = 0.f, zB1 = 0.f, zB2 = 0.f, zB3 = 0.f;

        #pragma unroll
        for (int c = 0; c < 4; ++c) {
            float c0 = 0.f, c1 = 0.f, c2 = 0.f, c3 = 0.f;
            float d0 = 0.f, d1 = 0.f, d2 = 0.f, d3 = 0.f;
            mma16816(c0, c1, c2, c3, a0, a1, a2, a3, B1f[2 * c].x, B1f[2 * c].y);
            mma16816(d0, d1, d2, d3, a0, a1, a2, a3, B1f[2 * c + 1].x, B1f[2 * c + 1].y);

            // packed |.|: cvt then one LOP3 clears both sign bits
            u32 h10 = bfpk(c0, c1) & ABS2;
            u32 h11 = bfpk(c2, c3) & ABS2;
            u32 h12 = bfpk(d0, d1) & ABS2;
            u32 h13 = bfpk(d2, d3) & ABS2;
            // h2 = |v| - bf16(|v|)  (abs folds into FADD operand modifier)
            u32 h20 = bfpk(fabsf(c0) - lo_bf(h10), fabsf(c1) - hi_bf(h10));
            u32 h21 = bfpk(fabsf(c2) - lo_bf(h11), fabsf(c3) - hi_bf(h11));
            u32 h22 = bfpk(fabsf(d0) - lo_bf(h12), fabsf(d1) - hi_bf(h12));
            u32 h23 = bfpk(fabsf(d2) - lo_bf(h13), fabsf(d3) - hi_bf(h13));

            mma16816(zA0, zA1, zA2, zA3, h10, h11, h12, h13, B2f[c].x, B2f[c].y);     // v1*h1
            mma16816(zB0, zB1, zB2, zB3, h20, h21, h22, h23, B2f[c].x, B2f[c].y);     // v1*h2
            mma16816(zB0, zB1, zB2, zB3, h10, h11, h12, h13, B2f[4 + c].x, B2f[4 + c].y); // v2*h1
        }
        mma16816(zA0, zA1, zA2, zA3, a0, a1, a2, a3, B2f[8].x, B2f[8].y);  // linear+bias

        float z0 = zA0 + zB0;
        float z1 = zA1 + zB1;
        float z2 = zA2 + zB2;
        float z3 = zA3 + zB3;

        float w0 = __shfl_down_sync(0xffffffffu, z0, 1);
        float w2 = __shfl_down_sync(0xffffffffu, z2, 1);

        if (tq == 0) {
            if (tokA < n) {
                float s0 = softplus_fast(z0);
                float s1 = softplus_fast(z1);
                float4 o;
                o.x = fmaf(s0, s0, 1e-9f);
                o.y = s0 * w0;
                o.z = o.y;
                o.w = fmaf(w0, w0, fmaf(s1, s1, 1e-9f));
                o4[tokA] = o;
            }
            if (tokB < n) {
                float s0 = softplus_fast(z2);
                float s1 = softplus_fast(z3);
                float4 o;
                o.x = fmaf(s0, s0, 1e-9f);
                o.y = s0 * w2;
                o.z = o.y;
                o.w = fmaf(w2, w2, fmaf(s1, s1, 1e-9f));
                o4[tokB] = o;
            }
        }
    }
}

extern "C" void kernel_launch(void* const* d_in, const int* in_sizes, int n_in,
                              void* d_out, int out_size)
{
    const float* x  = (const float*)d_in[0];
    const float* W1 = (const float*)d_in[1];
    const float* b1 = (const float*)d_in[2];
    const float* Wd = (const float*)d_in[3];
    const float* bd = (const float*)d_in[4];
    const float* Wo = (const float*)d_in[5];
    const float* bo = (const float*)d_in[6];
    float* out = (float*)d_out;

    int n = in_sizes[0] / 4;                 // tokens
    int ntiles = (n + 15) / 16;
    // one wave: 148 SMs x 6 blocks (reg-limited) -> each warp grid-strides
    int blocks = 148 * 6;
    int maxBlocks = (ntiles + 3) / 4;
    if (blocks > maxBlocks) blocks = maxBlocks;

    dln_prep<<<1, 544>>>(W1, b1, Wd, bd, Wo, bo);
    dln_mma<<<blocks, 128>>>(x, out, n);
}